// round 14
// baseline (speedup 1.0000x reference)
#include <cuda_runtime.h>
#include <cuda_bf16.h>
#include <stdint.h>

#define NNODES 8192
#define DIM    256
#define ALPHA  3.0f
#define NEG    0.2f

#define TPB  256                 // softmax threads per block (measured-best)
#define CPT  (NNODES / TPB)      // 32 columns per thread
#define VEC4 (CPT / 4)           // 8 float4 groups per thread

// Scratch (__device__ globals; no cudaMalloc allowed)
__device__ float g_s1[NNODES];
__device__ float g_s2p[NNODES];  // permuted: g_s2p[idx[j]] = s2[j]

// Single-op hardware tanh (sm_75+): MUFU.TANH, rel err ~2^-11 (<< 1e-3 budget)
__device__ __forceinline__ float htanh(float x) {
    float y;
    asm("tanh.approx.f32 %0, %1;" : "=f"(y) : "f"(x));
    return y;
}

// ---------------------------------------------------------------------------
// score: 8 LANES per node, 32 dims/lane -> 16 independent float4 loads per
// thread (MLP=16) issued back-to-back after the idx gather; DRAM latency is
// covered by depth instead of width. Reduction: 3 width-8 shuffles.
// 512 blocks x 256 threads (~7 blocks/SM). No barriers, no atomics.
// ---------------------------------------------------------------------------
__global__ void __launch_bounds__(256)
score_kernel(const int* __restrict__ idx,
             const float* __restrict__ e1,
             const float* __restrict__ e2,
             const float* __restrict__ w)
{
    const int node = (blockIdx.x * 256 + threadIdx.x) >> 3;   // 8 lanes/node
    const int sub  = threadIdx.x & 7;
    const int src  = __ldg(&idx[node]);

    const float4* r1 = (const float4*)(e1 + (size_t)src * DIM);
    const float4* r2 = (const float4*)(e2 + (size_t)src * DIM);
    const float4* w1 = (const float4*)(w);
    const float4* w2 = (const float4*)(w + DIM);

    // stage all 16 data loads first (maximum overlap), weights via L1
    float4 a[8], b[8];
    #pragma unroll
    for (int q = 0; q < 8; q++) {
        const int k = sub + 8 * q;            // interleaved -> coalesced
        a[q] = r1[k];
        b[q] = r2[k];
    }

    float p1 = 0.f, p2 = 0.f;
    #pragma unroll
    for (int q = 0; q < 8; q++) {
        const int k = sub + 8 * q;
        float4 wa = __ldg(&w1[k]);
        float4 wb = __ldg(&w2[k]);
        p1 += htanh(ALPHA * a[q].x) * wa.x + htanh(ALPHA * a[q].y) * wa.y
            + htanh(ALPHA * a[q].z) * wa.z + htanh(ALPHA * a[q].w) * wa.w;
        p2 += htanh(ALPHA * b[q].x) * wb.x + htanh(ALPHA * b[q].y) * wb.y
            + htanh(ALPHA * b[q].z) * wb.z + htanh(ALPHA * b[q].w) * wb.w;
    }
    // reduce within the 8-lane group
    #pragma unroll
    for (int o = 4; o > 0; o >>= 1) {
        p1 += __shfl_xor_sync(0xffffffffu, p1, o, 8);
        p2 += __shfl_xor_sync(0xffffffffu, p2, o, 8);
    }
    if (sub == 0) {
        g_s1[node] = p1;
        g_s2p[src] = p2;
    }
}

// ---------------------------------------------------------------------------
// softmax: one block per row i — R13 body UNCHANGED (at the LTS store cap).
// ---------------------------------------------------------------------------
__global__ void __launch_bounds__(TPB)
softmax_kernel(const float* __restrict__ att_b,
               float* __restrict__ out)
{
    const int i = blockIdx.x;
    const int t = threadIdx.x;

    // pre-dependency prologue: pure address math / parameter loads
    const float bias   = __ldg(att_b);
    float4*     row4   = (float4*)(out + (size_t)i * NNODES);
    const float4* s2p4 = (const float4*)g_s2p;

    // wait for score_kernel completion (PDL); no-op if launched normally
    cudaGridDependencySynchronize();

    const float base = g_s1[i] + bias;

    float vals[CPT];
    float sum = 0.f;
    #pragma unroll
    for (int q = 0; q < VEC4; q++) {
        float4 s = __ldg(&s2p4[q * TPB + t]);
        #pragma unroll
        for (int u = 0; u < 4; u++) {
            float x = base + ((const float*)&s)[u];
            x = (x > 0.f) ? x : NEG * x;      // leaky_relu
            float e = __expf(x);
            vals[q * 4 + u] = e;
            sum += e;
        }
    }

    // block sum (8 warps)
    __shared__ float shs[TPB / 32];
    #pragma unroll
    for (int o = 16; o > 0; o >>= 1)
        sum += __shfl_xor_sync(0xffffffffu, sum, o);
    if ((t & 31) == 0) shs[t >> 5] = sum;
    __syncthreads();
    sum = 0.f;
    #pragma unroll
    for (int wgi = 0; wgi < TPB / 32; wgi++) sum += shs[wgi];

    const float inv = __frcp_rn(sum);

    // contiguous float4 stores (plain, cached)
    #pragma unroll
    for (int q = 0; q < VEC4; q++) {
        float4 v;
        v.x = vals[q * 4 + 0] * inv;
        v.y = vals[q * 4 + 1] * inv;
        v.z = vals[q * 4 + 2] * inv;
        v.w = vals[q * 4 + 3] * inv;
        row4[q * TPB + t] = v;
    }
}

// ---------------------------------------------------------------------------
// Inputs: idx[int32 N], emb1_w[f32 N*D], emb2_w[f32 N*D], att_w[f32 2D],
//         att_b[f32 1].  Output: f32 N*N.
// ---------------------------------------------------------------------------
extern "C" void kernel_launch(void* const* d_in, const int* in_sizes, int n_in,
                              void* d_out, int out_size)
{
    const int*   idx  = (const int*)  d_in[0];
    const float* e1   = (const float*)d_in[1];
    const float* e2   = (const float*)d_in[2];
    const float* attw = (const float*)d_in[3];
    const float* attb = (const float*)d_in[4];
    float*       out  = (float*)d_out;

    score_kernel<<<NNODES * 8 / 256, 256>>>(idx, e1, e2, attw);

    // Programmatic dependent launch: softmax blocks spin up while the score
    // kernel drains; the device-side sync enforces the data dependency.
    cudaLaunchConfig_t cfg = {};
    cfg.gridDim  = dim3(NNODES, 1, 1);
    cfg.blockDim = dim3(TPB, 1, 1);
    cfg.dynamicSmemBytes = 0;
    cudaLaunchAttribute attr[1];
    attr[0].id = cudaLaunchAttributeProgrammaticStreamSerialization;
    attr[0].val.programmaticStreamSerializationAllowed = 1;
    cfg.attrs    = attr;
    cfg.numAttrs = 1;
    cudaError_t err = cudaLaunchKernelEx(&cfg, softmax_kernel, attb, out);
    if (err != cudaSuccess) {
        softmax_kernel<<<NNODES, TPB>>>(attb, out);   // identical semantics
    }
}